// round 2
// baseline (speedup 1.0000x reference)
#include <cuda_runtime.h>
#include <math.h>

#define VOCAB 50257
#define DMEAN 1024
#define DMV   1024
#define BATCH 32
#define SEQL  128

#define CK 128          // k-chunk for pass 2
#define KP 34           // padded smem row (34*4=136B: 8B-aligned rows, low bank conflict)
#define TILE_V 256      // v columns per block in pass 2
#define NB2 ((VOCAB + TILE_V - 1) / TILE_V)   // 197 blocks

// Scratch (device globals — no allocation allowed)
__device__ float g_h[BATCH * DMV];
__device__ float g_logits[BATCH * VOCAB];
__device__ float g_partial[BATCH];

// ---------------------------------------------------------------------------
// packed f32x2 helpers (Blackwell sm_100a)
// ---------------------------------------------------------------------------
__device__ __forceinline__ unsigned long long pack2(float w) {
    unsigned long long r;
    unsigned int wb = __float_as_uint(w);
    asm("mov.b64 %0, {%1, %1};" : "=l"(r) : "r"(wb));
    return r;
}
__device__ __forceinline__ void fma2(unsigned long long& acc,
                                     unsigned long long a,
                                     unsigned long long b) {
    asm("fma.rn.f32x2 %0, %1, %2, %0;" : "+l"(acc) : "l"(a), "l"(b));
}

// ---------------------------------------------------------------------------
// Kernel 1: h = gelu(z @ W0 + b0), exact GELU (erf form).
// Grid (16 j-tiles, 8 b-groups) x 256 threads. Deterministic, no atomics.
// ---------------------------------------------------------------------------
__global__ void __launch_bounds__(256) k1_gemm0(const float* __restrict__ z,
                                                const float* __restrict__ W0,
                                                const float* __restrict__ b0) {
    __shared__ float zs[4][DMEAN];
    const int tid = threadIdx.x;
    const int col = blockIdx.x * 64 + (tid & 63);
    const int bg  = blockIdx.y;
    const int brow = bg * 4 + (tid >> 6);

    for (int i = tid; i < 4 * DMEAN; i += 256) {
        int bb = i >> 10, kk = i & 1023;
        zs[bb][kk] = z[(bg * 4 + bb) * DMEAN + kk];
    }
    __syncthreads();

    const float* zr = zs[tid >> 6];
    const float* wp = W0 + col;
    float acc = 0.f;
#pragma unroll 8
    for (int k = 0; k < DMEAN; k++) {
        acc = fmaf(zr[k], wp[(size_t)k * DMV], acc);
    }
    float x = acc + b0[col];
    // exact GELU: 0.5*x*(1+erf(x/sqrt(2)))
    g_h[brow * DMV + col] = 0.5f * x * (1.f + erff(x * 0.70710678118654752f));
}

// ---------------------------------------------------------------------------
// Kernel 2: logits = h @ W1 + b1.  THE hot kernel (W1 = 206 MB).
// 197 blocks x 128 threads; each thread owns 2 vocab cols x 32 batch rows,
// accumulators packed as f32x2 batch-pairs (64 FMAs per 2 W1 loads).
// ---------------------------------------------------------------------------
__global__ void __launch_bounds__(128) k2_gemm1(const float* __restrict__ W1,
                                                const float* __restrict__ b1) {
    __shared__ float hs[CK][KP];
    const int tid = threadIdx.x;
    const int v0 = blockIdx.x * TILE_V + 2 * tid;
    const int v1 = v0 + 1;
    const int v0c = min(v0, VOCAB - 1);   // clamp so loads are always in-bounds
    const int v1c = min(v1, VOCAB - 1);

    unsigned long long acc0[16], acc1[16];
#pragma unroll
    for (int i = 0; i < 16; i++) { acc0[i] = 0ULL; acc1[i] = 0ULL; }

    for (int k0 = 0; k0 < DMV; k0 += CK) {
        __syncthreads();   // protect previous chunk's smem reads
        // stage h[0:32][k0:k0+128] into hs[kk][b]  (float4 global reads)
        {
            const int bb = tid >> 2;            // 32 batch rows x 4 threads each
            const int ks = (tid & 3) * 32;      // each thread: 32 consecutive k
            const float4* src =
                reinterpret_cast<const float4*>(&g_h[bb * DMV + k0 + ks]);
#pragma unroll
            for (int i = 0; i < 8; i++) {
                float4 q = src[i];
                hs[ks + 4 * i + 0][bb] = q.x;
                hs[ks + 4 * i + 1][bb] = q.y;
                hs[ks + 4 * i + 2][bb] = q.z;
                hs[ks + 4 * i + 3][bb] = q.w;
            }
        }
        __syncthreads();

        const float* w0p = W1 + (size_t)k0 * VOCAB + v0c;
        const float* w1p = W1 + (size_t)k0 * VOCAB + v1c;
#pragma unroll 4
        for (int kk = 0; kk < CK; kk++) {
            float w0 = w0p[(size_t)kk * VOCAB];
            float w1 = w1p[(size_t)kk * VOCAB];
            unsigned long long w00 = pack2(w0);
            unsigned long long w11 = pack2(w1);
#pragma unroll
            for (int bp = 0; bp < 16; bp++) {
                unsigned long long h2 =
                    *reinterpret_cast<const unsigned long long*>(&hs[kk][2 * bp]);
                fma2(acc0[bp], w00, h2);   // {b=2bp, b=2bp+1} for column v0
                fma2(acc1[bp], w11, h2);   // same pair for column v1
            }
        }
    }

    const float bias0 = b1[v0c];
    const float bias1 = b1[v1c];
#pragma unroll
    for (int bp = 0; bp < 16; bp++) {
        float lo0 = __uint_as_float((unsigned)(acc0[bp] & 0xffffffffu));
        float hi0 = __uint_as_float((unsigned)(acc0[bp] >> 32));
        float lo1 = __uint_as_float((unsigned)(acc1[bp] & 0xffffffffu));
        float hi1 = __uint_as_float((unsigned)(acc1[bp] >> 32));
        if (v0 < VOCAB) {
            g_logits[(size_t)(2 * bp) * VOCAB + v0]     = lo0 + bias0;
            g_logits[(size_t)(2 * bp + 1) * VOCAB + v0] = hi0 + bias0;
        }
        if (v1 < VOCAB) {
            g_logits[(size_t)(2 * bp) * VOCAB + v1]     = lo1 + bias1;
            g_logits[(size_t)(2 * bp + 1) * VOCAB + v1] = hi1 + bias1;
        }
    }
}

// ---------------------------------------------------------------------------
// Kernel 3: per-batch-row logsumexp + label gather (logits are L2-resident).
// labels are INT32 (jax without x64 silently downcasts jnp.int64 -> int32).
// partial[b] = SEQL * LSE_b  -  sum_s logits[b, labels[b,s]]
// ---------------------------------------------------------------------------
__global__ void __launch_bounds__(512) k3_lse(const int* __restrict__ labels) {
    const int b = blockIdx.x;
    const int tid = threadIdx.x;
    const float* row = g_logits + (size_t)b * VOCAB;
    __shared__ float red[512];

    float m = -INFINITY;
    for (int v = tid; v < VOCAB; v += 512) m = fmaxf(m, row[v]);
    red[tid] = m; __syncthreads();
    for (int s = 256; s > 0; s >>= 1) {
        if (tid < s) red[tid] = fmaxf(red[tid], red[tid + s]);
        __syncthreads();
    }
    const float M = red[0]; __syncthreads();

    float ssum = 0.f;
    for (int v = tid; v < VOCAB; v += 512) ssum += expf(row[v] - M);
    red[tid] = ssum; __syncthreads();
    for (int s = 256; s > 0; s >>= 1) {
        if (tid < s) red[tid] += red[tid + s];
        __syncthreads();
    }
    const float Ssum = red[0]; __syncthreads();

    float g = 0.f;
    if (tid < SEQL) {
        int lv = labels[b * SEQL + tid];
        lv = max(0, min(lv, VOCAB - 1));   // defensive clamp (no fault on dtype surprise)
        g = row[lv];
    }
    red[tid] = g; __syncthreads();
    for (int s = 256; s > 0; s >>= 1) {
        if (tid < s) red[tid] += red[tid + s];
        __syncthreads();
    }
    if (tid == 0) {
        g_partial[b] = (float)SEQL * (M + logf(Ssum)) - red[0];
    }
}

// ---------------------------------------------------------------------------
// Kernel 4: final mean (deterministic serial sum of 32 values).
// ---------------------------------------------------------------------------
__global__ void k4_final(float* __restrict__ out) {
    if (threadIdx.x == 0) {
        float s = 0.f;
        for (int i = 0; i < BATCH; i++) s += g_partial[i];
        out[0] = s / (float)(BATCH * SEQL);
    }
}

// ---------------------------------------------------------------------------
extern "C" void kernel_launch(void* const* d_in, const int* in_sizes, int n_in,
                              void* d_out, int out_size) {
    const float* z      = (const float*)d_in[0];
    const int*   labels = (const int*)d_in[1];
    const float* W0     = (const float*)d_in[2];
    const float* b0     = (const float*)d_in[3];
    const float* W1     = (const float*)d_in[4];
    const float* b1     = (const float*)d_in[5];
    float* out = (float*)d_out;

    k1_gemm0<<<dim3(16, 8), 256>>>(z, W0, b0);
    k2_gemm1<<<NB2, 128>>>(W1, b1);
    k3_lse<<<BATCH, 512>>>(labels);
    k4_final<<<1, 32>>>(out);
}

// round 3
// speedup vs baseline: 1.7083x; 1.7083x over previous
#include <cuda_runtime.h>
#include <math.h>
#include <stdint.h>

#define VOCAB 50257
#define DMEAN 1024
#define DMV   1024
#define BATCH 32
#define SEQL  128

// ---- k2 pipeline config ----
#define TV     256                 // vocab cols per block
#define KS     16                  // k rows per stage
#define DEPTH  4                   // smem pipeline stages
#define KSPLIT 2                   // split-K factor
#define KB     (DMV / KSPLIT)      // 512 k per block
#define NSTAGE (KB / KS)           // 32 stages
#define NBV    ((VOCAB + TV - 1) / TV)   // 197
#define K2_SMEM (DEPTH * KS * (TV + BATCH) * 4)   // 73728 B

// Scratch (device globals — no runtime allocation allowed)
__device__ float g_ht[DMV * BATCH];                 // h transposed: [k][b]
__device__ float g_part[KSPLIT][BATCH][VOCAB];      // split-K partial logits
__device__ float g_partial[BATCH];

// ---------------------------------------------------------------------------
// helpers
// ---------------------------------------------------------------------------
__device__ __forceinline__ unsigned long long pack2(float w) {
    unsigned long long r;
    unsigned int wb = __float_as_uint(w);
    asm("mov.b64 %0, {%1, %1};" : "=l"(r) : "r"(wb));
    return r;
}
__device__ __forceinline__ void fma2(unsigned long long& acc,
                                     unsigned long long a,
                                     unsigned long long b) {
    asm("fma.rn.f32x2 %0, %1, %2, %0;" : "+l"(acc) : "l"(a), "l"(b));
}
__device__ __forceinline__ void cp_async4(uint32_t dst_smem, const void* src) {
    asm volatile("cp.async.ca.shared.global [%0], [%1], 4;"
                 :: "r"(dst_smem), "l"(src) : "memory");
}
#define CP_COMMIT() asm volatile("cp.async.commit_group;" ::: "memory")
#define CP_WAIT(n)  asm volatile("cp.async.wait_group %0;" :: "n"(n) : "memory")

// ---------------------------------------------------------------------------
// Kernel 1: h = gelu(z @ W0 + b0), stored K-MAJOR into g_ht[k][b].
// grid (16,8) x 256 thr; unroll 32 for deep MLP on the W0 column stream.
// ---------------------------------------------------------------------------
__global__ void __launch_bounds__(256) k1_gemm0(const float* __restrict__ z,
                                                const float* __restrict__ W0,
                                                const float* __restrict__ b0) {
    __shared__ float zs[4][DMEAN];
    const int tid = threadIdx.x;
    const int col = blockIdx.x * 64 + (tid & 63);
    const int bg  = blockIdx.y;
    const int brow = bg * 4 + (tid >> 6);

    for (int i = tid; i < 4 * DMEAN; i += 256) {
        int bb = i >> 10, kk = i & 1023;
        zs[bb][kk] = z[(bg * 4 + bb) * DMEAN + kk];
    }
    __syncthreads();

    const float* zr = zs[tid >> 6];
    const float* wp = W0 + col;
    float acc = 0.f;
#pragma unroll 32
    for (int k = 0; k < DMEAN; k++) {
        acc = fmaf(zr[k], wp[(size_t)k * DMV], acc);
    }
    float x = acc + b0[col];
    float g = 0.5f * x * (1.f + erff(x * 0.70710678118654752f));
    g_ht[col * BATCH + brow] = g;     // k-major for coalesced staging in k2
}

// ---------------------------------------------------------------------------
// Kernel 2: partial logits = h @ W1 (bias deferred to k3).
// grid (197, KSPLIT) x 128 thr. 4-stage cp.async pipeline:
//   ws[DEPTH][KS][TV]   : W1 tile (coalesced 4B cp.async; VOCAB row stride is
//                          only 4B-aligned so 4B is the widest legal copy)
//   hs[DEPTH][KS][BATCH]: h-chunk (coalesced from k-major g_ht)
// Inner loop per kk: LDS.64 w-pair + 16 broadcast LDS.64 h-pairs + 32 fma2.
// fma pipe is the intended limiter (64 cyc) vs LSU (36 cyc).
// ---------------------------------------------------------------------------
__global__ void __launch_bounds__(128, 3) k2_gemm1(const float* __restrict__ W1) {
    extern __shared__ float sm[];
    float* ws = sm;                              // [DEPTH][KS][TV]
    float* hs = sm + DEPTH * KS * TV;            // [DEPTH][KS][BATCH]
    const uint32_t smb = (uint32_t)__cvta_generic_to_shared(sm);
    const uint32_t hsb = smb + DEPTH * KS * TV * 4;

    const int t  = threadIdx.x;
    const int vb = blockIdx.x * TV;
    const int ky = blockIdx.y;
    const int k0g = ky * KB;

    unsigned long long acc0[16], acc1[16];
#pragma unroll
    for (int i = 0; i < 16; i++) { acc0[i] = 0ULL; acc1[i] = 0ULL; }

    // ---- stage issue: 32 W1 words + 4 h words per thread ----
    auto issue = [&](int s) {
        const int buf = s & (DEPTH - 1);
        const int kr = k0g + s * KS;
#pragma unroll
        for (int i = 0; i < 32; i++) {
            int idx = i * 128 + t;
            int r = idx >> 8, c = idx & 255;
            int vc = vb + c; if (vc > VOCAB - 1) vc = VOCAB - 1;  // tail clamp
            cp_async4(smb + (((buf * KS + r) * TV + c) << 2),
                      W1 + (size_t)(kr + r) * VOCAB + vc);
        }
#pragma unroll
        for (int i = 0; i < 4; i++) {
            int idx = i * 128 + t;
            int r = idx >> 5, b = idx & 31;
            cp_async4(hsb + (((buf * KS + r) * BATCH + b) << 2),
                      g_ht + (kr + r) * BATCH + b);
        }
        CP_COMMIT();
    };

    issue(0); issue(1); issue(2);

    for (int s = 0; s < NSTAGE; s++) {
        CP_WAIT(2);
        __syncthreads();
        if (s + 3 < NSTAGE) issue(s + 3);

        const int buf = s & (DEPTH - 1);
        const float* wrow = ws + (buf * KS) * TV + 2 * t;
        const float* hrow = hs + (buf * KS) * BATCH;
#pragma unroll
        for (int kk = 0; kk < KS; kk++) {
            float2 w = *reinterpret_cast<const float2*>(wrow + kk * TV);
            unsigned long long wa = pack2(w.x);
            unsigned long long wb = pack2(w.y);
            const float* hk = hrow + kk * BATCH;
#pragma unroll
            for (int bp = 0; bp < 16; bp++) {
                unsigned long long h2 =
                    *reinterpret_cast<const unsigned long long*>(hk + 2 * bp);
                fma2(acc0[bp], wa, h2);
                fma2(acc1[bp], wb, h2);
            }
        }
    }

    const int v0 = vb + 2 * t;
    const int v1 = v0 + 1;
#pragma unroll
    for (int bp = 0; bp < 16; bp++) {
        float lo0 = __uint_as_float((unsigned)(acc0[bp] & 0xffffffffu));
        float hi0 = __uint_as_float((unsigned)(acc0[bp] >> 32));
        float lo1 = __uint_as_float((unsigned)(acc1[bp] & 0xffffffffu));
        float hi1 = __uint_as_float((unsigned)(acc1[bp] >> 32));
        if (v0 < VOCAB) {
            g_part[ky][2 * bp][v0]     = lo0;
            g_part[ky][2 * bp + 1][v0] = hi0;
        }
        if (v1 < VOCAB) {
            g_part[ky][2 * bp][v1]     = lo1;
            g_part[ky][2 * bp + 1][v1] = hi1;
        }
    }
}

// ---------------------------------------------------------------------------
// Kernel 3: per-row logsumexp + label gather on (part0 + part1 + bias).
// Partials are L2-resident (12.9 MB x 2 passes).
// ---------------------------------------------------------------------------
__global__ void __launch_bounds__(512) k3_lse(const int* __restrict__ labels,
                                              const float* __restrict__ b1) {
    const int b = blockIdx.x;
    const int tid = threadIdx.x;
    const float* r0 = &g_part[0][b][0];
    const float* r1 = &g_part[1][b][0];
    __shared__ float red[512];

    float m = -INFINITY;
    for (int v = tid; v < VOCAB; v += 512)
        m = fmaxf(m, r0[v] + r1[v] + b1[v]);
    red[tid] = m; __syncthreads();
    for (int s = 256; s > 0; s >>= 1) {
        if (tid < s) red[tid] = fmaxf(red[tid], red[tid + s]);
        __syncthreads();
    }
    const float M = red[0]; __syncthreads();

    float ssum = 0.f;
    for (int v = tid; v < VOCAB; v += 512)
        ssum += expf(r0[v] + r1[v] + b1[v] - M);
    red[tid] = ssum; __syncthreads();
    for (int s = 256; s > 0; s >>= 1) {
        if (tid < s) red[tid] += red[tid + s];
        __syncthreads();
    }
    const float Ssum = red[0]; __syncthreads();

    float g = 0.f;
    if (tid < SEQL) {
        int lv = labels[b * SEQL + tid];
        lv = max(0, min(lv, VOCAB - 1));
        g = r0[lv] + r1[lv] + b1[lv];
    }
    red[tid] = g; __syncthreads();
    for (int s = 256; s > 0; s >>= 1) {
        if (tid < s) red[tid] += red[tid + s];
        __syncthreads();
    }
    if (tid == 0) {
        g_partial[b] = (float)SEQL * (M + logf(Ssum)) - red[0];
    }
}

// ---------------------------------------------------------------------------
// Kernel 4: final mean (deterministic serial sum).
// ---------------------------------------------------------------------------
__global__ void k4_final(float* __restrict__ out) {
    if (threadIdx.x == 0) {
        float s = 0.f;
        for (int i = 0; i < BATCH; i++) s += g_partial[i];
        out[0] = s / (float)(BATCH * SEQL);
    }
}

// ---------------------------------------------------------------------------
extern "C" void kernel_launch(void* const* d_in, const int* in_sizes, int n_in,
                              void* d_out, int out_size) {
    const float* z      = (const float*)d_in[0];
    const int*   labels = (const int*)d_in[1];
    const float* W0     = (const float*)d_in[2];
    const float* b0     = (const float*)d_in[3];
    const float* W1     = (const float*)d_in[4];
    const float* b1     = (const float*)d_in[5];
    float* out = (float*)d_out;

    // opt-in to 72KB dynamic smem (idempotent; host-side, capture-safe)
    cudaFuncSetAttribute(k2_gemm1, cudaFuncAttributeMaxDynamicSharedMemorySize,
                         K2_SMEM);

    k1_gemm0<<<dim3(16, 8), 256>>>(z, W0, b0);
    k2_gemm1<<<dim3(NBV, KSPLIT), 128, K2_SMEM>>>(W1);
    k3_lse<<<BATCH, 512>>>(labels, b1);
    k4_final<<<1, 32>>>(out);
}

// round 5
// speedup vs baseline: 2.2016x; 1.2887x over previous
#include <cuda_runtime.h>
#include <cuda_bf16.h>
#include <math.h>
#include <stdint.h>

#define VOCAB 50257
#define DMEAN 1024
#define DMV   1024
#define BATCH 32
#define SEQL  128

#define TM      128                       // M tile (vocab / dmv rows)
#define KC      64                        // k per chunk
#define NCHUNK  16                        // 1024 / 64
#define NBV     ((VOCAB + TM - 1) / TM)   // 393
#define AW      36                        // padded words per 64-bf16 row (144B)
#define ABUF_W  (TM * AW)                 // 4608 words per A buffer
#define BBUF_W  (BATCH * AW)              // 1152 words per B buffer
#define SMEM_BYTES ((2 * ABUF_W + 2 * BBUF_W) * 4)   // 46080

// Scratch (device globals — no runtime allocation allowed)
__device__ __nv_bfloat16 g_hb[BATCH * DMV];   // h bf16, [b][k]
__device__ float g_logits[BATCH * VOCAB];
__device__ float g_partial[BATCH];

// ---------------------------------------------------------------------------
// PTX helpers (all sm_80-era: ldmatrix / mma.sync / cp.async)
// ---------------------------------------------------------------------------
#define LDSM4(d0, d1, d2, d3, a)                                               \
    asm volatile("ldmatrix.sync.aligned.m8n8.x4.shared.b16 {%0,%1,%2,%3}, [%4];" \
                 : "=r"(d0), "=r"(d1), "=r"(d2), "=r"(d3) : "r"(a))

#define MMA16816(c, a, bb0, bb1)                                               \
    asm volatile("mma.sync.aligned.m16n8k16.row.col.f32.bf16.bf16.f32 "        \
                 "{%0,%1,%2,%3}, {%4,%5,%6,%7}, {%8,%9}, {%0,%1,%2,%3};"       \
                 : "+f"(c[0]), "+f"(c[1]), "+f"(c[2]), "+f"(c[3])              \
                 : "r"(a[0]), "r"(a[1]), "r"(a[2]), "r"(a[3]),                 \
                   "r"(bb0), "r"(bb1))

__device__ __forceinline__ void cp_async16(uint32_t dst, const void* src) {
    asm volatile("cp.async.ca.shared.global [%0], [%1], 16;"
                 :: "r"(dst), "l"(src) : "memory");
}
__device__ __forceinline__ uint32_t cvt_bf16x2(float hi, float lo) {
    uint32_t pk;
    asm("cvt.rn.bf16x2.f32 %0, %1, %2;" : "=r"(pk) : "f"(hi), "f"(lo));
    return pk;
}
__device__ __forceinline__ void sts32(uint32_t addr, uint32_t v) {
    asm volatile("st.shared.b32 [%0], %1;" :: "r"(addr), "r"(v));
}

// store W1/W0 chunk regs -> A buffer, bank-conflict-free (temporal permutation)
__device__ __forceinline__ void stsA(uint32_t abase, int t, const float* f) {
    const uint32_t rb = abase + (uint32_t)t * (AW * 4);
#pragma unroll
    for (int s = 0; s < 32; s++) {
        int wd = (s + (t >> 3)) & 31;
        sts32(rb + wd * 4, cvt_bf16x2(f[2 * wd + 1], f[2 * wd]));
    }
}

// ---------------------------------------------------------------------------
// Kernel 1: h = gelu(z @ W0 + b0) -> g_hb[b][k] bf16.  mma.sync, 8 blocks.
// A[m][k] = W0[k][mb+m] (transpose-load), B[n][k] = z[n][k] (cvt in-kernel).
// ---------------------------------------------------------------------------
__global__ void __launch_bounds__(128) k1_mma(const float* __restrict__ z,
                                              const float* __restrict__ W0,
                                              const float* __restrict__ b0) {
    extern __shared__ char sm[];
    const uint32_t smb = (uint32_t)__cvta_generic_to_shared(sm);
    const int t = threadIdx.x, w = t >> 5, lane = t & 31;
    const int mb0 = blockIdx.x * TM;
    const int colg = mb0 + t;

    float f[KC];
    auto loadA = [&](int c) {
        const float* p = W0 + (size_t)c * KC * DMV + colg;
#pragma unroll
        for (int j = 0; j < KC; j++) f[j] = __ldg(p + (size_t)j * DMV);
    };
    auto fillB = [&](int c, int nb) {
        const uint32_t base = smb + (2 * ABUF_W + nb * BBUF_W) * 4;
#pragma unroll
        for (int i = 0; i < 8; i++) {
            int n = (t >> 5) + 4 * i;
            int wd = t & 31;
            float2 zz = *reinterpret_cast<const float2*>(
                z + (size_t)n * DMEAN + c * KC + 2 * wd);
            sts32(base + (n * AW + wd) * 4, cvt_bf16x2(zz.y, zz.x));
        }
    };

    loadA(0);
    fillB(0, 0);
    stsA(smb, t, f);
    loadA(1);
    __syncthreads();

    float acc[2][4][4];
#pragma unroll
    for (int i = 0; i < 2; i++)
#pragma unroll
        for (int j = 0; j < 4; j++)
#pragma unroll
            for (int q = 0; q < 4; q++) acc[i][j][q] = 0.f;

    for (int c = 0; c < NCHUNK; c++) {
        const int buf = c & 1, nb = buf ^ 1;
        if (c + 1 < NCHUNK) fillB(c + 1, nb);

        const uint32_t Ab = smb + buf * ABUF_W * 4;
        const uint32_t Bb = smb + (2 * ABUF_W + buf * BBUF_W) * 4;
#pragma unroll
        for (int ks = 0; ks < 4; ks++) {
            uint32_t a[2][4], bfr[2][4];
#pragma unroll
            for (int ms = 0; ms < 2; ms++) {
                int row = w * 32 + ms * 16 + (lane & 15);
                int wd = ks * 8 + ((lane >> 4) << 2);
                LDSM4(a[ms][0], a[ms][1], a[ms][2], a[ms][3],
                      Ab + (row * AW + wd) * 4);
            }
#pragma unroll
            for (int ng = 0; ng < 2; ng++) {
                int n = ng * 16 + (lane & 7) + ((lane >> 4) << 3);
                int wd = ks * 8 + (((lane >> 3) & 1) << 2);
                LDSM4(bfr[ng][0], bfr[ng][1], bfr[ng][2], bfr[ng][3],
                      Bb + (n * AW + wd) * 4);
            }
#pragma unroll
            for (int ms = 0; ms < 2; ms++)
#pragma unroll
                for (int ns = 0; ns < 4; ns++)
                    MMA16816(acc[ms][ns], a[ms],
                             bfr[ns >> 1][(ns & 1) * 2],
                             bfr[ns >> 1][(ns & 1) * 2 + 1]);
        }
        if (c + 1 < NCHUNK) {
            stsA(smb + nb * ABUF_W * 4, t, f);
            if (c + 2 < NCHUNK) loadA(c + 2);
            __syncthreads();
        }
    }

    // epilogue: x + bias -> gelu -> bf16 -> g_hb[b][m]
#pragma unroll
    for (int ms = 0; ms < 2; ms++) {
        int m0 = mb0 + w * 32 + ms * 16 + (lane >> 2);
        int m1 = m0 + 8;
        float bv0 = b0[m0], bv1 = b0[m1];
#pragma unroll
        for (int ns = 0; ns < 4; ns++) {
            int b = ns * 8 + (lane & 3) * 2;
            float x;
            x = acc[ms][ns][0] + bv0;
            g_hb[(size_t)b * DMV + m0] =
                __float2bfloat16(0.5f * x * (1.f + erff(x * 0.70710678118654752f)));
            x = acc[ms][ns][1] + bv0;
            g_hb[(size_t)(b + 1) * DMV + m0] =
                __float2bfloat16(0.5f * x * (1.f + erff(x * 0.70710678118654752f)));
            x = acc[ms][ns][2] + bv1;
            g_hb[(size_t)b * DMV + m1] =
                __float2bfloat16(0.5f * x * (1.f + erff(x * 0.70710678118654752f)));
            x = acc[ms][ns][3] + bv1;
            g_hb[(size_t)(b + 1) * DMV + m1] =
                __float2bfloat16(0.5f * x * (1.f + erff(x * 0.70710678118654752f)));
        }
    }
}

// ---------------------------------------------------------------------------
// Kernel 2: logits = h @ W1 + b1.  mma.sync bf16, 393 blocks, DRAM-bound.
// ---------------------------------------------------------------------------
__global__ void __launch_bounds__(128) k2_mma(const float* __restrict__ W1,
                                              const float* __restrict__ b1) {
    extern __shared__ char sm[];
    const uint32_t smb = (uint32_t)__cvta_generic_to_shared(sm);
    const int t = threadIdx.x, w = t >> 5, lane = t & 31;
    const int vb = blockIdx.x * TM;
    const int vg = min(vb + t, VOCAB - 1);

    float f[KC];
    auto loadA = [&](int c) {
        const float* p = W1 + (size_t)c * KC * VOCAB + vg;
#pragma unroll
        for (int j = 0; j < KC; j++) f[j] = __ldg(p + (size_t)j * VOCAB);
    };
    auto fillB = [&](int c, int nb) {
        const uint32_t base = smb + (2 * ABUF_W + nb * BBUF_W) * 4;
#pragma unroll
        for (int i = 0; i < 2; i++) {
            int idx = t + i * 128;
            int n = idx >> 3, g = idx & 7;
            cp_async16(base + (uint32_t)(n * 144 + g * 16),
                       g_hb + (size_t)n * DMV + c * KC + g * 8);
        }
        asm volatile("cp.async.commit_group;" ::: "memory");
    };

    loadA(0);
    fillB(0, 0);
    stsA(smb, t, f);
    loadA(1);
    asm volatile("cp.async.wait_group 0;" ::: "memory");
    __syncthreads();

    float acc[2][4][4];
#pragma unroll
    for (int i = 0; i < 2; i++)
#pragma unroll
        for (int j = 0; j < 4; j++)
#pragma unroll
            for (int q = 0; q < 4; q++) acc[i][j][q] = 0.f;

    for (int c = 0; c < NCHUNK; c++) {
        const int buf = c & 1, nb = buf ^ 1;
        if (c + 1 < NCHUNK) fillB(c + 1, nb);

        const uint32_t Ab = smb + buf * ABUF_W * 4;
        const uint32_t Bb = smb + (2 * ABUF_W + buf * BBUF_W) * 4;
#pragma unroll
        for (int ks = 0; ks < 4; ks++) {
            uint32_t a[2][4], bfr[2][4];
#pragma unroll
            for (int ms = 0; ms < 2; ms++) {
                int row = w * 32 + ms * 16 + (lane & 15);
                int wd = ks * 8 + ((lane >> 4) << 2);
                LDSM4(a[ms][0], a[ms][1], a[ms][2], a[ms][3],
                      Ab + (row * AW + wd) * 4);
            }
#pragma unroll
            for (int ng = 0; ng < 2; ng++) {
                int n = ng * 16 + (lane & 7) + ((lane >> 4) << 3);
                int wd = ks * 8 + (((lane >> 3) & 1) << 2);
                LDSM4(bfr[ng][0], bfr[ng][1], bfr[ng][2], bfr[ng][3],
                      Bb + (n * AW + wd) * 4);
            }
#pragma unroll
            for (int ms = 0; ms < 2; ms++)
#pragma unroll
                for (int ns = 0; ns < 4; ns++)
                    MMA16816(acc[ms][ns], a[ms],
                             bfr[ns >> 1][(ns & 1) * 2],
                             bfr[ns >> 1][(ns & 1) * 2 + 1]);
        }
        if (c + 1 < NCHUNK) {
            stsA(smb + nb * ABUF_W * 4, t, f);
            if (c + 2 < NCHUNK) loadA(c + 2);
            asm volatile("cp.async.wait_group 0;" ::: "memory");
            __syncthreads();
        }
    }

    // epilogue: + bias, store g_logits[b][v] (guard vocab tail)
#pragma unroll
    for (int ms = 0; ms < 2; ms++) {
        int v0 = vb + w * 32 + ms * 16 + (lane >> 2);
        int v1 = v0 + 8;
        float bi0 = b1[min(v0, VOCAB - 1)];
        float bi1 = b1[min(v1, VOCAB - 1)];
#pragma unroll
        for (int ns = 0; ns < 4; ns++) {
            int b = ns * 8 + (lane & 3) * 2;
            if (v0 < VOCAB) {
                g_logits[(size_t)b * VOCAB + v0]       = acc[ms][ns][0] + bi0;
                g_logits[(size_t)(b + 1) * VOCAB + v0] = acc[ms][ns][1] + bi0;
            }
            if (v1 < VOCAB) {
                g_logits[(size_t)b * VOCAB + v1]       = acc[ms][ns][2] + bi1;
                g_logits[(size_t)(b + 1) * VOCAB + v1] = acc[ms][ns][3] + bi1;
            }
        }
    }
}

// ---------------------------------------------------------------------------
// Kernel 3: per-row logsumexp + label gather.
// ---------------------------------------------------------------------------
__global__ void __launch_bounds__(512) k3_lse(const int* __restrict__ labels) {
    const int b = blockIdx.x;
    const int tid = threadIdx.x;
    const float* row = g_logits + (size_t)b * VOCAB;
    __shared__ float red[512];

    float m = -INFINITY;
    for (int v = tid; v < VOCAB; v += 512) m = fmaxf(m, row[v]);
    red[tid] = m; __syncthreads();
    for (int s = 256; s > 0; s >>= 1) {
        if (tid < s) red[tid] = fmaxf(red[tid], red[tid + s]);
        __syncthreads();
    }
    const float M = red[0]; __syncthreads();

    float ssum = 0.f;
    for (int v = tid; v < VOCAB; v += 512) ssum += expf(row[v] - M);
    red[tid] = ssum; __syncthreads();
    for (int s = 256; s > 0; s >>= 1) {
        if (tid < s) red[tid] += red[tid + s];
        __syncthreads();
    }
    const float Ssum = red[0]; __syncthreads();

    float g = 0.f;
    if (tid < SEQL) {
        int lv = labels[b * SEQL + tid];
        lv = max(0, min(lv, VOCAB - 1));
        g = row[lv];
    }
    red[tid] = g; __syncthreads();
    for (int s = 256; s > 0; s >>= 1) {
        if (tid < s) red[tid] += red[tid + s];
        __syncthreads();
    }
    if (tid == 0) g_partial[b] = (float)SEQL * (M + logf(Ssum)) - red[0];
}

// ---------------------------------------------------------------------------
// Kernel 4: final mean.
// ---------------------------------------------------------------------------
__global__ void k4_final(float* __restrict__ out) {
    if (threadIdx.x == 0) {
        float s = 0.f;
        for (int i = 0; i < BATCH; i++) s += g_partial[i];
        out[0] = s / (float)(BATCH * SEQL);
    }
}

// ---------------------------------------------------------------------------
extern "C" void kernel_launch(void* const* d_in, const int* in_sizes, int n_in,
                              void* d_out, int out_size) {
    const float* z      = (const float*)d_in[0];
    const int*   labels = (const int*)d_in[1];
    const float* W0     = (const float*)d_in[2];
    const float* b0     = (const float*)d_in[3];
    const float* W1     = (const float*)d_in[4];
    const float* b1     = (const float*)d_in[5];
    float* out = (float*)d_out;

    k1_mma<<<DMV / TM, 128, SMEM_BYTES>>>(z, W0, b0);      // 8 blocks
    k2_mma<<<NBV, 128, SMEM_BYTES>>>(W1, b1);              // 393 blocks
    k3_lse<<<BATCH, 512>>>(labels);
    k4_final<<<1, 32>>>(out);
}